// round 10
// baseline (speedup 1.0000x reference)
#include <cuda_runtime.h>

// OpenLSTM: B=4096 sequences, T=1024, HID=16, PROJ=2.
// t < 256 teacher-forced; t >= 256 recurrent.
//
// R10 hybrid (base R5 = 191.5us):
//  - Recurrent: radix-4 all-reduce (2 rounds x 3 parallel shfl_xor{1,2,3},
//    {4,8,12}) -> butterfly chain 120 -> ~75cyc. Recurrent is chain-bound
//    (R9 proved it: +30cyc chain erased a 4-SHFL instr saving).
//  - Teacher: R9 segregated reduction (4 SHFL/step, branch-free direct
//    stores) -- teacher is throughput-bound, chain hidden by TU=4.
// Layout: TPE=16, 2 elem/warp, 2048 warps (3.46/SMSP). Folded sigmoids.

#define T_TOTAL 1024
#define N_CTX   256
#define TPE     16
#define EPB     4     // elements per 64-thread block
#define TU      4     // teacher-phase time unroll

__device__ __forceinline__ float tanh_fast(float x) {
    float y;
    asm("tanh.approx.f32 %0, %1;" : "=f"(y) : "f"(x));
    return y;
}

__global__ void __launch_bounds__(64)
open_lstm_kernel(const float* __restrict__ u,     // (B, T, 4)
                 const float* __restrict__ w_ih,  // (64, 2)
                 const float* __restrict__ w_hh,  // (64, 2)
                 const float* __restrict__ b_ih,  // (64)
                 const float* __restrict__ b_hh,  // (64)
                 const float* __restrict__ w_hr,  // (2, 16)
                 float* __restrict__ out)         // (B, T, 2)
{
    const int tid  = threadIdx.x;
    const int j    = tid & (TPE - 1);                 // hidden unit 0..15
    const int e    = blockIdx.x * EPB + (tid >> 4);   // element index
    const bool lo8 = (j < 8);

    // Weights for unit j. sigma(x)=0.5*tanh(0.5x)+0.5 folded: i/f/o gate rows
    // pre-scaled by 0.5; o-path outer 0.5 folded into w_hr.
    float wi[4][2], wh[4][2], bb[4], wr0, wr1;
#pragma unroll
    for (int k = 0; k < 4; k++) {
        const int r = k * 16 + j;
        const float sc = (k == 2) ? 1.0f : 0.5f;
        wi[k][0] = w_ih[r * 2 + 0] * sc;
        wi[k][1] = w_ih[r * 2 + 1] * sc;
        wh[k][0] = w_hh[r * 2 + 0] * sc;
        wh[k][1] = w_hh[r * 2 + 1] * sc;
        bb[k]    = (b_ih[r] + b_hh[r]) * sc;
    }
    wr0 = w_hr[j]      * 0.5f;
    wr1 = w_hr[16 + j] * 0.5f;

    const float4* __restrict__ up = (const float4*)u + (size_t)e * T_TOTAL;
    float2* __restrict__ op       = (float2*)out + (size_t)e * T_TOTAL;
    float* __restrict__ opf       = (float*)op;
    const int so = (j >> 3) & 1;   // teacher store slot: 0 -> h.x, 1 -> h.y

    float c = 0.0f;
    float s_last = 0.0f;           // teacher: segregated h (p0 lanes<8, p1 lanes>=8)

    // ================= teacher-forced phase (R9 style), unrolled x4 ==========
#pragma unroll 1
    for (int t = 0; t < N_CTX; t += TU) {
        float4 vv[TU];
#pragma unroll
        for (int s = 0; s < TU; s++) vv[s] = up[t + s];

        float gg[TU][4];
#pragma unroll
        for (int s = 0; s < TU; s++)
#pragma unroll
            for (int k = 0; k < 4; k++)
                gg[s][k] = fmaf(wi[k][0], vv[s].x,
                           fmaf(wi[k][1], vv[s].y,
                           fmaf(wh[k][0], vv[s].z,
                           fmaf(wh[k][1], vv[s].w, bb[k]))));

        float ti[TU], tf[TU], tg[TU], to[TU];
#pragma unroll
        for (int s = 0; s < TU; s++) {
            ti[s] = tanh_fast(gg[s][0]);
            tf[s] = tanh_fast(gg[s][1]);
            tg[s] = tanh_fast(gg[s][2]);
            to[s] = tanh_fast(gg[s][3]);
        }

        float tc[TU];
#pragma unroll
        for (int s = 0; s < TU; s++) {
            float ca = fmaf(tf[s], c, c);            // 2*sigma(f)*c
            float cb = fmaf(ti[s], tg[s], tg[s]);    // 2*sigma(i)*tanh(g)
            c = fmaf(0.5f, ca, 0.5f * cb);
            tc[s] = tanh_fast(c);
        }

        float sr[TU];
#pragma unroll
        for (int s = 0; s < TU; s++) {
            float b0 = fmaf(wr0, to[s], wr0);        // wr0*(1+to)
            float b1 = fmaf(wr1, to[s], wr1);
            float p0 = b0 * tc[s];
            float p1 = b1 * tc[s];
            // segregate: lanes<8 accumulate p0, lanes>=8 accumulate p1
            float send = lo8 ? p1 : p0;
            float keep = lo8 ? p0 : p1;
            float r = keep + __shfl_xor_sync(0xffffffffu, send, 8);
            r += __shfl_xor_sync(0xffffffffu, r, 1);
            r += __shfl_xor_sync(0xffffffffu, r, 2);
            r += __shfl_xor_sync(0xffffffffu, r, 4);
            sr[s] = r;
        }
        // branch-free scalar stores: lanes<8 write .x, lanes>=8 write .y
#pragma unroll
        for (int s = 0; s < TU; s++)
            opf[2 * (t + s) + so] = sr[s];
        s_last = sr[TU - 1];
    }

    // phase boundary: broadcast final teacher h into all lanes
    float oth = __shfl_xor_sync(0xffffffffu, s_last, 8);
    float H0 = lo8 ? s_last : oth;
    float H1 = lo8 ? oth : s_last;

    // ================= recurrent phase: radix-4 all-reduce ===================
    float4 v = up[N_CTX];
    float xp[4];
#pragma unroll
    for (int k = 0; k < 4; k++)
        xp[k] = fmaf(wi[k][0], v.x, fmaf(wi[k][1], v.y, bb[k]));

#pragma unroll 2
    for (int t = N_CTX; t < T_TOTAL; t++) {
        float4 vn = up[(t + 1 < T_TOTAL) ? (t + 1) : t];

        float gi  = fmaf(wh[0][0], H0, fmaf(wh[0][1], H1, xp[0]));
        float gf  = fmaf(wh[1][0], H0, fmaf(wh[1][1], H1, xp[1]));
        float gg2 = fmaf(wh[2][0], H0, fmaf(wh[2][1], H1, xp[2]));
        float go  = fmaf(wh[3][0], H0, fmaf(wh[3][1], H1, xp[3]));

        float ti = tanh_fast(gi);
        float tf = tanh_fast(gf);
        float tg = tanh_fast(gg2);
        float to = tanh_fast(go);

        float ca = fmaf(tf, c, c);
        float cb = fmaf(ti, tg, tg);
        c = fmaf(0.5f, ca, 0.5f * cb);

        float tc = tanh_fast(c);
        float b0 = fmaf(wr0, to, wr0);   // off critical chain
        float b1 = fmaf(wr1, to, wr1);

        float p0 = b0 * tc;
        float p1 = b1 * tc;

        // radix-4 all-reduce over 16 lanes: 2 rounds, 3 parallel shfls each
        {
            float a1 = __shfl_xor_sync(0xffffffffu, p0, 1);
            float a2 = __shfl_xor_sync(0xffffffffu, p0, 2);
            float a3 = __shfl_xor_sync(0xffffffffu, p0, 3);
            float c1 = __shfl_xor_sync(0xffffffffu, p1, 1);
            float c2 = __shfl_xor_sync(0xffffffffu, p1, 2);
            float c3 = __shfl_xor_sync(0xffffffffu, p1, 3);
            p0 = (p0 + a1) + (a2 + a3);
            p1 = (p1 + c1) + (c2 + c3);
            float d1 = __shfl_xor_sync(0xffffffffu, p0, 4);
            float d2 = __shfl_xor_sync(0xffffffffu, p0, 8);
            float d3 = __shfl_xor_sync(0xffffffffu, p0, 12);
            float e1 = __shfl_xor_sync(0xffffffffu, p1, 4);
            float e2 = __shfl_xor_sync(0xffffffffu, p1, 8);
            float e3 = __shfl_xor_sync(0xffffffffu, p1, 12);
            p0 = (p0 + d1) + (d2 + d3);
            p1 = (p1 + e1) + (e2 + e3);
        }

        H0 = p0; H1 = p1;
        if (j == 0) op[t] = make_float2(p0, p1);

        // next step's x-part (off critical chain)
#pragma unroll
        for (int k = 0; k < 4; k++)
            xp[k] = fmaf(wi[k][0], vn.x, fmaf(wi[k][1], vn.y, bb[k]));
        v = vn;
    }
}

extern "C" void kernel_launch(void* const* d_in, const int* in_sizes, int n_in,
                              void* d_out, int out_size)
{
    const float* u    = (const float*)d_in[0];
    const float* w_ih = (const float*)d_in[1];
    const float* w_hh = (const float*)d_in[2];
    const float* b_ih = (const float*)d_in[3];
    const float* b_hh = (const float*)d_in[4];
    const float* w_hr = (const float*)d_in[5];
    float* out = (float*)d_out;

    const int B = in_sizes[0] / (T_TOTAL * 4);   // 4096
    const int grid = B / EPB;                    // 1024 blocks x 64 threads

    open_lstm_kernel<<<grid, 64>>>(u, w_ih, w_hh, b_ih, b_hh, w_hr, out);
}

// round 11
// speedup vs baseline: 1.0189x; 1.0189x over previous
#include <cuda_runtime.h>

// OpenLSTM: B=4096 sequences, T=1024, HID=16, PROJ=2.
// t < 256 teacher-forced; t >= 256 recurrent.
//
// R11 = consolidation of measured-best pieces:
//  - Teacher: R9 segregated reduction (4 SHFL/step) + branch-free stores.
//  - Recurrent: R5 butterfly (measured optimum across R5/R9/R10 shapes),
//    now with branch-free SEL store, peeled last step (no clamp), unroll 4.
// Layout: TPE=16, 2 elem/warp, 2048 warps (3.46/SMSP). Folded sigmoids.

#define T_TOTAL 1024
#define N_CTX   256
#define TPE     16
#define EPB     4     // elements per 64-thread block
#define TU      4     // teacher-phase time unroll

__device__ __forceinline__ float tanh_fast(float x) {
    float y;
    asm("tanh.approx.f32 %0, %1;" : "=f"(y) : "f"(x));
    return y;
}

__global__ void __launch_bounds__(64)
open_lstm_kernel(const float* __restrict__ u,     // (B, T, 4)
                 const float* __restrict__ w_ih,  // (64, 2)
                 const float* __restrict__ w_hh,  // (64, 2)
                 const float* __restrict__ b_ih,  // (64)
                 const float* __restrict__ b_hh,  // (64)
                 const float* __restrict__ w_hr,  // (2, 16)
                 float* __restrict__ out)         // (B, T, 2)
{
    const int tid  = threadIdx.x;
    const int j    = tid & (TPE - 1);                 // hidden unit 0..15
    const int e    = blockIdx.x * EPB + (tid >> 4);   // element index
    const bool lo8 = (j < 8);

    // Weights for unit j. sigma(x)=0.5*tanh(0.5x)+0.5 folded: i/f/o gate rows
    // pre-scaled by 0.5; o-path outer 0.5 folded into w_hr.
    float wi[4][2], wh[4][2], bb[4], wr0, wr1;
#pragma unroll
    for (int k = 0; k < 4; k++) {
        const int r = k * 16 + j;
        const float sc = (k == 2) ? 1.0f : 0.5f;
        wi[k][0] = w_ih[r * 2 + 0] * sc;
        wi[k][1] = w_ih[r * 2 + 1] * sc;
        wh[k][0] = w_hh[r * 2 + 0] * sc;
        wh[k][1] = w_hh[r * 2 + 1] * sc;
        bb[k]    = (b_ih[r] + b_hh[r]) * sc;
    }
    wr0 = w_hr[j]      * 0.5f;
    wr1 = w_hr[16 + j] * 0.5f;

    const float4* __restrict__ up = (const float4*)u + (size_t)e * T_TOTAL;
    float* __restrict__ opf       = (float*)out + (size_t)e * T_TOTAL * 2;
    const int so = (j >> 3) & 1;   // store slot: lanes<8 -> h.x, lanes>=8 -> h.y

    float c = 0.0f;
    float s_last = 0.0f;           // teacher: segregated h (p0 lanes<8, p1 lanes>=8)

    // ================= teacher-forced phase (R9 style), unrolled x4 ==========
#pragma unroll 1
    for (int t = 0; t < N_CTX; t += TU) {
        float4 vv[TU];
#pragma unroll
        for (int s = 0; s < TU; s++) vv[s] = up[t + s];

        float gg[TU][4];
#pragma unroll
        for (int s = 0; s < TU; s++)
#pragma unroll
            for (int k = 0; k < 4; k++)
                gg[s][k] = fmaf(wi[k][0], vv[s].x,
                           fmaf(wi[k][1], vv[s].y,
                           fmaf(wh[k][0], vv[s].z,
                           fmaf(wh[k][1], vv[s].w, bb[k]))));

        float ti[TU], tf[TU], tg[TU], to[TU];
#pragma unroll
        for (int s = 0; s < TU; s++) {
            ti[s] = tanh_fast(gg[s][0]);
            tf[s] = tanh_fast(gg[s][1]);
            tg[s] = tanh_fast(gg[s][2]);
            to[s] = tanh_fast(gg[s][3]);
        }

        float tc[TU];
#pragma unroll
        for (int s = 0; s < TU; s++) {
            float ca = fmaf(tf[s], c, c);            // 2*sigma(f)*c
            float cb = fmaf(ti[s], tg[s], tg[s]);    // 2*sigma(i)*tanh(g)
            c = fmaf(0.5f, ca, 0.5f * cb);
            tc[s] = tanh_fast(c);
        }

        float sr[TU];
#pragma unroll
        for (int s = 0; s < TU; s++) {
            float b0 = fmaf(wr0, to[s], wr0);        // wr0*(1+to)
            float b1 = fmaf(wr1, to[s], wr1);
            float p0 = b0 * tc[s];
            float p1 = b1 * tc[s];
            // segregate: lanes<8 accumulate p0, lanes>=8 accumulate p1
            float send = lo8 ? p1 : p0;
            float keep = lo8 ? p0 : p1;
            float r = keep + __shfl_xor_sync(0xffffffffu, send, 8);
            r += __shfl_xor_sync(0xffffffffu, r, 1);
            r += __shfl_xor_sync(0xffffffffu, r, 2);
            r += __shfl_xor_sync(0xffffffffu, r, 4);
            sr[s] = r;
        }
        // branch-free scalar stores
#pragma unroll
        for (int s = 0; s < TU; s++)
            opf[2 * (t + s) + so] = sr[s];
        s_last = sr[TU - 1];
    }

    // phase boundary: broadcast final teacher h into all lanes
    float oth = __shfl_xor_sync(0xffffffffu, s_last, 8);
    float H0 = lo8 ? s_last : oth;
    float H1 = lo8 ? oth : s_last;

    // ================= recurrent phase: R5 butterfly, branch-free store ======
    float4 v = up[N_CTX];
    float xp[4];
#pragma unroll
    for (int k = 0; k < 4; k++)
        xp[k] = fmaf(wi[k][0], v.x, fmaf(wi[k][1], v.y, bb[k]));

#pragma unroll 4
    for (int t = N_CTX; t < T_TOTAL - 1; t++) {
        float4 vn = up[t + 1];      // peeled last iter -> no clamp needed

        float gi  = fmaf(wh[0][0], H0, fmaf(wh[0][1], H1, xp[0]));
        float gf  = fmaf(wh[1][0], H0, fmaf(wh[1][1], H1, xp[1]));
        float gg2 = fmaf(wh[2][0], H0, fmaf(wh[2][1], H1, xp[2]));
        float go  = fmaf(wh[3][0], H0, fmaf(wh[3][1], H1, xp[3]));

        float ti = tanh_fast(gi);
        float tf = tanh_fast(gf);
        float tg = tanh_fast(gg2);
        float to = tanh_fast(go);

        float ca = fmaf(tf, c, c);
        float cb = fmaf(ti, tg, tg);
        c = fmaf(0.5f, ca, 0.5f * cb);

        float tc = tanh_fast(c);
        float b0 = fmaf(wr0, to, wr0);   // off critical chain
        float b1 = fmaf(wr1, to, wr1);

        float p0 = b0 * tc;
        float p1 = b1 * tc;
        // R5 butterfly all-reduce (measured-optimal shape)
#pragma unroll
        for (int k = 1; k < TPE; k <<= 1) {
            p0 += __shfl_xor_sync(0xffffffffu, p0, k, TPE);
            p1 += __shfl_xor_sync(0xffffffffu, p1, k, TPE);
        }
        H0 = p0; H1 = p1;

        // branch-free store: lanes<8 write h.x, lanes>=8 write h.y
        opf[2 * t + so] = lo8 ? p0 : p1;

        // next step's x-part (off critical chain)
#pragma unroll
        for (int k = 0; k < 4; k++)
            xp[k] = fmaf(wi[k][0], vn.x, fmaf(wi[k][1], vn.y, bb[k]));
        v = vn;
    }

    // peeled final step (t = T_TOTAL-1)
    {
        const int t = T_TOTAL - 1;
        float gi  = fmaf(wh[0][0], H0, fmaf(wh[0][1], H1, xp[0]));
        float gf  = fmaf(wh[1][0], H0, fmaf(wh[1][1], H1, xp[1]));
        float gg2 = fmaf(wh[2][0], H0, fmaf(wh[2][1], H1, xp[2]));
        float go  = fmaf(wh[3][0], H0, fmaf(wh[3][1], H1, xp[3]));

        float ti = tanh_fast(gi);
        float tf = tanh_fast(gf);
        float tg = tanh_fast(gg2);
        float to = tanh_fast(go);

        float ca = fmaf(tf, c, c);
        float cb = fmaf(ti, tg, tg);
        c = fmaf(0.5f, ca, 0.5f * cb);

        float tc = tanh_fast(c);
        float b0 = fmaf(wr0, to, wr0);
        float b1 = fmaf(wr1, to, wr1);

        float p0 = b0 * tc;
        float p1 = b1 * tc;
#pragma unroll
        for (int k = 1; k < TPE; k <<= 1) {
            p0 += __shfl_xor_sync(0xffffffffu, p0, k, TPE);
            p1 += __shfl_xor_sync(0xffffffffu, p1, k, TPE);
        }
        opf[2 * t + so] = lo8 ? p0 : p1;
    }
}

extern "C" void kernel_launch(void* const* d_in, const int* in_sizes, int n_in,
                              void* d_out, int out_size)
{
    const float* u    = (const float*)d_in[0];
    const float* w_ih = (const float*)d_in[1];
    const float* w_hh = (const float*)d_in[2];
    const float* b_ih = (const float*)d_in[3];
    const float* b_hh = (const float*)d_in[4];
    const float* w_hr = (const float*)d_in[5];
    float* out = (float*)d_out;

    const int B = in_sizes[0] / (T_TOTAL * 4);   // 4096
    const int grid = B / EPB;                    // 1024 blocks x 64 threads

    open_lstm_kernel<<<grid, 64>>>(u, w_ih, w_hh, b_ih, b_hh, w_hr, out);
}